// round 14
// baseline (speedup 1.0000x reference)
#include <cuda_runtime.h>
#include <math.h>
#include <stdint.h>

#define B_  4
#define S_  2048
#define D_  2048
#define H_  16
#define DH_ 128
#define M_  (B_*S_)

// Scratch (allowed: __device__ globals)
__device__ float g_q[(size_t)B_*H_*S_*DH_];    // Q [bh][s][dh]  (unroped)
__device__ float g_k[(size_t)B_*H_*S_*DH_];    // K [bh][s][dh]  (unroped)
__device__ float g_v[(size_t)B_*H_*S_*DH_];    // V [bh][dh][s]  (TRANSPOSED, tf32)
__device__ float g_ctx[(size_t)B_*S_*D_];
__device__ float g_xr[(size_t)M_*D_];          // tf32 x; later reused as roped-K
__device__ float g_wr3[(size_t)3*D_*D_];       // tf32 wq|wk|wv concatenated; wo uses [0]
__device__ float g_cos[(size_t)S_*64];
__device__ float g_sin[(size_t)S_*64];

// ---------------------------------------------------------------------------
// Helpers
// ---------------------------------------------------------------------------
__device__ __forceinline__ uint32_t tf32u(float x) {
    uint32_t r;
    asm("cvt.rna.tf32.f32 %0, %1;" : "=r"(r) : "f"(x));
    return r;
}
__device__ __forceinline__ float f2tf32(float x) { return __uint_as_float(tf32u(x)); }

__device__ __forceinline__ void mma_tf32(float c[4], const uint32_t a[4], const uint32_t b[2]) {
    asm volatile(
        "mma.sync.aligned.m16n8k8.row.col.f32.tf32.tf32.f32 "
        "{%0,%1,%2,%3}, {%4,%5,%6,%7}, {%8,%9}, {%0,%1,%2,%3};"
        : "+f"(c[0]), "+f"(c[1]), "+f"(c[2]), "+f"(c[3])
        : "r"(a[0]), "r"(a[1]), "r"(a[2]), "r"(a[3]), "r"(b[0]), "r"(b[1]));
}

__device__ __forceinline__ void cp16(uint32_t dst, const void* src) {
    asm volatile("cp.async.cg.shared.global [%0], [%1], 16;" :: "r"(dst), "l"(src));
}

// ---------------------------------------------------------------------------
// Pre-round: out[i] = tf32(in[i])
// ---------------------------------------------------------------------------
__global__ __launch_bounds__(256)
void preround_kernel(const float* __restrict__ in, float* __restrict__ out)
{
    const int i = blockIdx.x * blockDim.x + threadIdx.x;
    float4 v = ((const float4*)in)[i];
    v.x = f2tf32(v.x); v.y = f2tf32(v.y);
    v.z = f2tf32(v.z); v.w = f2tf32(v.w);
    ((float4*)out)[i] = v;
}

// ---------------------------------------------------------------------------
// TF32 GEMM: 128x256 CTA tile, 256 threads (2x4 warps, 64x64 warp tile),
// BK=32, 2-stage cp.async. A, W pre-rounded tf32. Stride-36 smem rows.
// OUT=0: flat C0 = A·Wᵀ + b0  (N = gridDim.x*256)
// OUT=1: merged QKV (N=6144): per-CTA which = n0>>11 selects dest/bias;
//        q,k -> heads [bh][s][dh]; v -> transposed [bh][dh][s] + tf32.
// ---------------------------------------------------------------------------
#define GBK 32
#define GEMM_SMEM ((2*128*36 + 2*256*36) * 4)   // 110592 B

template<int OUT>
__global__ __launch_bounds__(256)
void gemm_tf32(const float* __restrict__ A, const float* __restrict__ W,
               const float* __restrict__ b0, const float* __restrict__ b1,
               const float* __restrict__ b2,
               float* __restrict__ C0, float* __restrict__ C1, float* __restrict__ C2)
{
    extern __shared__ float smg[];
    float (*As)[128][36] = (float(*)[128][36])smg;              // [2][128][36]
    float (*Ws)[256][36] = (float(*)[256][36])(smg + 2*128*36); // [2][256][36]

    const int K  = D_;
    const int m0 = blockIdx.y * 128;
    const int n0 = blockIdx.x * 256;
    const int tid  = threadIdx.x;
    const int warp = tid >> 5, lane = tid & 31;
    const int wy = warp >> 2, wx = warp & 3;    // 2x4 warp grid
    const int lr = lane >> 2, lc = lane & 3;

    float acc[4][8][4];
#pragma unroll
    for (int ti = 0; ti < 4; ti++)
#pragma unroll
        for (int nt = 0; nt < 8; nt++)
#pragma unroll
            for (int e = 0; e < 4; e++) acc[ti][nt][e] = 0.f;

    auto issue = [&](int st, int k0) {
#pragma unroll
        for (int u = 0; u < 4; u++) {           // A: 1024 chunks
            const int f = tid + u * 256;
            const int r = f >> 3, c4 = f & 7;
            cp16((uint32_t)__cvta_generic_to_shared(&As[st][r][c4 * 4]),
                 A + (size_t)(m0 + r) * K + k0 + c4 * 4);
        }
#pragma unroll
        for (int u = 0; u < 8; u++) {           // W: 2048 chunks
            const int f = tid + u * 256;
            const int r = f >> 3, c4 = f & 7;
            cp16((uint32_t)__cvta_generic_to_shared(&Ws[st][r][c4 * 4]),
                 W + (size_t)(n0 + r) * K + k0 + c4 * 4);
        }
        asm volatile("cp.async.commit_group;");
    };

    issue(0, 0);

    const int NIT = K / GBK;                    // 64
#pragma unroll 1
    for (int it = 0; it < NIT; it++) {
        asm volatile("cp.async.wait_group 0;");
        __syncthreads();
        if (it + 1 < NIT) issue((it + 1) & 1, (it + 1) * GBK);
        const int cur = it & 1;

#pragma unroll
        for (int kk = 0; kk < GBK; kk += 8) {
            uint32_t afr[4][4], bfr[8][2];
            const int ac = kk + lc;
#pragma unroll
            for (int ti = 0; ti < 4; ti++) {
                const int ar = wy * 64 + ti * 16 + lr;
                afr[ti][0] = __float_as_uint(As[cur][ar    ][ac]);
                afr[ti][1] = __float_as_uint(As[cur][ar + 8][ac]);
                afr[ti][2] = __float_as_uint(As[cur][ar    ][ac + 4]);
                afr[ti][3] = __float_as_uint(As[cur][ar + 8][ac + 4]);
            }
#pragma unroll
            for (int nt = 0; nt < 8; nt++) {
                const int br = wx * 64 + nt * 8 + lr;
                bfr[nt][0] = __float_as_uint(Ws[cur][br][ac]);
                bfr[nt][1] = __float_as_uint(Ws[cur][br][ac + 4]);
            }
#pragma unroll
            for (int ti = 0; ti < 4; ti++)
#pragma unroll
                for (int nt = 0; nt < 8; nt++)
                    mma_tf32(acc[ti][nt], afr[ti], bfr[nt]);
        }
    }

    // ---- epilogue: whole CTA lies in one 2048-col segment for OUT=1 ----
    const int which = n0 >> 11;                       // 0=q, 1=k, 2=v
    const float* bias = (OUT == 1) ? (which == 0 ? b0 : which == 1 ? b1 : b2) : b0;
    float* Cqk = (which == 0) ? C0 : C1;

#pragma unroll
    for (int ti = 0; ti < 4; ti++) {
#pragma unroll
        for (int nt = 0; nt < 8; nt++) {
            const int row = m0 + wy * 64 + ti * 16 + lr;
            const int col = n0 + wx * 64 + nt * 8 + lc * 2;
#pragma unroll
            for (int e = 0; e < 4; e++) {
                const int m = row + (e >> 1) * 8;
                const int n = col + (e & 1);
                const int nn = n & 2047;
                const float v = acc[ti][nt][e] + bias[OUT == 1 ? nn : n];
                if (OUT == 1) {
                    const int bb = m >> 11, s = m & (S_ - 1);
                    const int h = nn >> 7, dh = nn & 127;
                    if (which == 2)
                        C2[(((size_t)(bb * H_ + h)) * DH_ + dh) * S_ + s] = f2tf32(v);
                    else
                        Cqk[(((size_t)bb * H_ + h) * S_ + s) * DH_ + dh] = v;
                } else {
                    C0[(size_t)m * D_ + n] = v;
                }
            }
        }
    }
}

// ---------------------------------------------------------------------------
// RoPE table + K pre-rope (roped, tf32, into g_xr)
// ---------------------------------------------------------------------------
__global__ __launch_bounds__(256)
void rope_table_kernel()
{
    const int idx = blockIdx.x * blockDim.x + threadIdx.x;
    const int p = idx & 63;
    const int s = idx >> 6;
    const float invf = (float)exp(-(double)p * (log(10000.0) / 64.0));
    const float ang  = (float)s * invf;
    g_cos[idx] = (float)cos((double)ang);
    g_sin[idx] = (float)sin((double)ang);
}

__global__ __launch_bounds__(256)
void rope_k_kernel()
{
    const int idx = blockIdx.x * blockDim.x + threadIdx.x;  // B*H*S*64
    const int p   = idx & 63;
    const int row = idx >> 6;
    const int s   = row & (S_ - 1);
    const float cs = g_cos[s * 64 + p];
    const float sn = g_sin[s * 64 + p];
    const float* kb = g_k + (size_t)row * DH_;
    float* kr = g_xr + (size_t)row * DH_;
    const float k1 = kb[p], k2 = kb[p + 64];
    kr[p]      = f2tf32(k1 * cs - k2 * sn);
    kr[p + 64] = f2tf32(k2 * cs + k1 * sn);
}

// ---------------------------------------------------------------------------
// TF32 flash attention v3 (R11/R12-proven): 256 threads / 8 warps,
// 128 q-rows/CTA, 64-key KV tiles double-buffered via cp.async.
// ---------------------------------------------------------------------------
#define KPAD 132
#define VPAD 68
#define PPAD 76
#define SMEM_ATTN ((128*KPAD + 2*128*VPAD + 128*PPAD) * 4)

__global__ __launch_bounds__(256)
void attn_mma(float* __restrict__ ctx)
{
    extern __shared__ float sm[];
    float* KB = sm;                        // 128*KPAD (2 x 64-row buffers)
    float* VB = sm + 128 * KPAD;           // 2 x 128*VPAD
    float* Ps = VB + 2 * 128 * VPAD;       // 128*PPAD

    const int bh  = blockIdx.y;
    const int m0  = blockIdx.x * 128;
    const int tid = threadIdx.x;
    const int warp = tid >> 5, lane = tid & 31;
    const int lr = lane >> 2, lc = lane & 3;
    const int qr = warp * 16;

    const float* Qb = g_q  + (size_t)bh * S_ * DH_;
    const float* Kr = g_xr + (size_t)bh * S_ * DH_;       // roped, tf32
    const float* Vt = g_v  + (size_t)bh * DH_ * S_;       // [dh][s], tf32

    const float scale = 0.08838834764831845f;   // 1/sqrt(128)

    // ---- stage Q with fused rope, scaled, tf32, into KB ----
#pragma unroll
    for (int i = 0; i < 8; i++) {
        const int idx = tid + i * 256;      // 128 rows x 16 pair-chunks
        const int r  = idx >> 4;
        const int p4 = idx & 15;
        const int s  = m0 + r;
        const float4 v1 = *(const float4*)(Qb + (size_t)s * DH_ + p4 * 4);
        const float4 v2 = *(const float4*)(Qb + (size_t)s * DH_ + p4 * 4 + 64);
        const float4 cs = *(const float4*)(g_cos + s * 64 + p4 * 4);
        const float4 sn = *(const float4*)(g_sin + s * 64 + p4 * 4);
        float4 o1, o2;
        o1.x = f2tf32((v1.x * cs.x - v2.x * sn.x) * scale);
        o1.y = f2tf32((v1.y * cs.y - v2.y * sn.y) * scale);
        o1.z = f2tf32((v1.z * cs.z - v2.z * sn.z) * scale);
        o1.w = f2tf32((v1.w * cs.w - v2.w * sn.w) * scale);
        o2.x = f2tf32((v2.x * cs.x + v1.x * sn.x) * scale);
        o2.y = f2tf32((v2.y * cs.y + v1.y * sn.y) * scale);
        o2.z = f2tf32((v2.z * cs.z + v1.z * sn.z) * scale);
        o2.w = f2tf32((v2.w * cs.w + v1.w * sn.w) * scale);
        *(float4*)(&KB[r * KPAD + p4 * 4])      = o1;
        *(float4*)(&KB[r * KPAD + p4 * 4 + 64]) = o2;
    }
    __syncthreads();
    uint32_t qf[16][4];
#pragma unroll
    for (int ks = 0; ks < 16; ks++) {
        qf[ks][0] = __float_as_uint(KB[(qr + lr    ) * KPAD + ks * 8 + lc    ]);
        qf[ks][1] = __float_as_uint(KB[(qr + lr + 8) * KPAD + ks * 8 + lc    ]);
        qf[ks][2] = __float_as_uint(KB[(qr + lr    ) * KPAD + ks * 8 + lc + 4]);
        qf[ks][3] = __float_as_uint(KB[(qr + lr + 8) * KPAD + ks * 8 + lc + 4]);
    }
    __syncthreads();   // Q fully consumed before K tiles overwrite KB

    auto issue_tile = [&](int t) {
        const int buf = t & 1;
        const int key0 = t * 64;
        float* kb = KB + buf * 64 * KPAD;
        float* vb = VB + buf * 128 * VPAD;
#pragma unroll
        for (int u = 0; u < 8; u++) {
            const int c = tid + u * 256;
            const int r = c >> 5, c4 = c & 31;
            cp16((uint32_t)__cvta_generic_to_shared(&kb[r * KPAD + c4 * 4]),
                 Kr + (size_t)(key0 + r) * DH_ + c4 * 4);
        }
#pragma unroll
        for (int u = 0; u < 8; u++) {
            const int c = tid + u * 256;
            const int r = c >> 4, c4 = c & 15;
            cp16((uint32_t)__cvta_generic_to_shared(&vb[r * VPAD + c4 * 4]),
                 Vt + (size_t)r * S_ + key0 + c4 * 4);
        }
        asm volatile("cp.async.commit_group;");
    };

    issue_tile(0);
    issue_tile(1);

    float oacc[16][4];
#pragma unroll
    for (int nt = 0; nt < 16; nt++)
#pragma unroll
        for (int e = 0; e < 4; e++) oacc[nt][e] = 0.f;
    float mr0 = -1e30f, mr1 = -1e30f, lsum0 = 0.f, lsum1 = 0.f;

#pragma unroll 1
    for (int kt = 0; kt < 32; kt++) {
        asm volatile("cp.async.wait_group %0;" :: "n"(1));
        __syncthreads();
        const int buf = kt & 1;
        const float* kb = KB + buf * 64 * KPAD;
        const float* vb = VB + buf * 128 * VPAD;

        float sacc[8][4];
#pragma unroll
        for (int n = 0; n < 8; n++)
#pragma unroll
            for (int e = 0; e < 4; e++) sacc[n][e] = 0.f;
#pragma unroll
        for (int ks = 0; ks < 16; ks++) {
#pragma unroll
            for (int n = 0; n < 8; n++) {
                uint32_t b[2];
                b[0] = __float_as_uint(kb[(n * 8 + lr) * KPAD + ks * 8 + lc    ]);
                b[1] = __float_as_uint(kb[(n * 8 + lr) * KPAD + ks * 8 + lc + 4]);
                mma_tf32(sacc[n], qf[ks], b);
            }
        }

        float mx0 = mr0, mx1 = mr1;
#pragma unroll
        for (int n = 0; n < 8; n++) {
            mx0 = fmaxf(mx0, fmaxf(sacc[n][0], sacc[n][1]));
            mx1 = fmaxf(mx1, fmaxf(sacc[n][2], sacc[n][3]));
        }
        mx0 = fmaxf(mx0, __shfl_xor_sync(0xffffffffu, mx0, 1));
        mx0 = fmaxf(mx0, __shfl_xor_sync(0xffffffffu, mx0, 2));
        mx1 = fmaxf(mx1, __shfl_xor_sync(0xffffffffu, mx1, 1));
        mx1 = fmaxf(mx1, __shfl_xor_sync(0xffffffffu, mx1, 2));
        const float f0 = __expf(mr0 - mx0);
        const float f1 = __expf(mr1 - mx1);
        mr0 = mx0; mr1 = mx1;

        float s0 = 0.f, s1 = 0.f;
#pragma unroll
        for (int n = 0; n < 8; n++) {
            const float p0 = __expf(sacc[n][0] - mx0);
            const float p1 = __expf(sacc[n][1] - mx0);
            const float p2 = __expf(sacc[n][2] - mx1);
            const float p3 = __expf(sacc[n][3] - mx1);
            s0 += p0 + p1; s1 += p2 + p3;
            float2 lo; lo.x = f2tf32(p0); lo.y = f2tf32(p1);
            *(float2*)(&Ps[(qr + lr    ) * PPAD + n * 8 + lc * 2]) = lo;
            float2 hi; hi.x = f2tf32(p2); hi.y = f2tf32(p3);
            *(float2*)(&Ps[(qr + lr + 8) * PPAD + n * 8 + lc * 2]) = hi;
        }
        s0 += __shfl_xor_sync(0xffffffffu, s0, 1);
        s0 += __shfl_xor_sync(0xffffffffu, s0, 2);
        s1 += __shfl_xor_sync(0xffffffffu, s1, 1);
        s1 += __shfl_xor_sync(0xffffffffu, s1, 2);
        lsum0 = lsum0 * f0 + s0;
        lsum1 = lsum1 * f1 + s1;
#pragma unroll
        for (int nt = 0; nt < 16; nt++) {
            oacc[nt][0] *= f0; oacc[nt][1] *= f0;
            oacc[nt][2] *= f1; oacc[nt][3] *= f1;
        }
        __syncwarp();

#pragma unroll
        for (int kk = 0; kk < 8; kk++) {
            uint32_t af[4];
            af[0] = __float_as_uint(Ps[(qr + lr    ) * PPAD + kk * 8 + lc    ]);
            af[1] = __float_as_uint(Ps[(qr + lr + 8) * PPAD + kk * 8 + lc    ]);
            af[2] = __float_as_uint(Ps[(qr + lr    ) * PPAD + kk * 8 + lc + 4]);
            af[3] = __float_as_uint(Ps[(qr + lr + 8) * PPAD + kk * 8 + lc + 4]);
#pragma unroll
            for (int nt = 0; nt < 16; nt++) {
                uint32_t b[2];
                b[0] = __float_as_uint(vb[(nt * 8 + lr) * VPAD + kk * 8 + lc    ]);
                b[1] = __float_as_uint(vb[(nt * 8 + lr) * VPAD + kk * 8 + lc + 4]);
                mma_tf32(oacc[nt], af, b);
            }
        }

        __syncthreads();
        if (kt + 2 < 32) {
            issue_tile(kt + 2);
        } else {
            asm volatile("cp.async.commit_group;");
        }
    }

    const float i0 = 1.f / lsum0, i1 = 1.f / lsum1;
    const int bb = bh >> 4, h = bh & 15;
    const int gr0 = m0 + qr + lr;
    float* o0 = ctx + ((size_t)bb * S_ + gr0) * D_ + h * DH_;
    float* o1 = o0 + (size_t)8 * D_;
#pragma unroll
    for (int nt = 0; nt < 16; nt++) {
        float2 a; a.x = f2tf32(oacc[nt][0] * i0); a.y = f2tf32(oacc[nt][1] * i0);
        *(float2*)(o0 + nt * 8 + lc * 2) = a;
        float2 b; b.x = f2tf32(oacc[nt][2] * i1); b.y = f2tf32(oacc[nt][3] * i1);
        *(float2*)(o1 + nt * 8 + lc * 2) = b;
    }
}

// ---------------------------------------------------------------------------
extern "C" void kernel_launch(void* const* d_in, const int* in_sizes, int n_in,
                              void* d_out, int out_size)
{
    const float* x  = (const float*)d_in[0];
    const float* wq = (const float*)d_in[1];
    const float* bq = (const float*)d_in[2];
    const float* wk = (const float*)d_in[3];
    const float* bk = (const float*)d_in[4];
    const float* wv = (const float*)d_in[5];
    const float* bv = (const float*)d_in[6];
    const float* wo = (const float*)d_in[7];
    const float* bo = (const float*)d_in[8];
    float* out = (float*)d_out;

    float *q, *k, *v, *ctx, *xr, *wr3;
    cudaGetSymbolAddress((void**)&q,   g_q);
    cudaGetSymbolAddress((void**)&k,   g_k);
    cudaGetSymbolAddress((void**)&v,   g_v);
    cudaGetSymbolAddress((void**)&ctx, g_ctx);
    cudaGetSymbolAddress((void**)&xr,  g_xr);
    cudaGetSymbolAddress((void**)&wr3, g_wr3);

    cudaFuncSetAttribute(attn_mma, cudaFuncAttributeMaxDynamicSharedMemorySize, SMEM_ATTN);
    cudaFuncSetAttribute(gemm_tf32<0>, cudaFuncAttributeMaxDynamicSharedMemorySize, GEMM_SMEM);
    cudaFuncSetAttribute(gemm_tf32<1>, cudaFuncAttributeMaxDynamicSharedMemorySize, GEMM_SMEM);

    const int XB = (M_ * D_) / 4 / 256;
    const int WB = (D_ * D_) / 4 / 256;

    rope_table_kernel<<<(S_ * 64) / 256, 256>>>();
    preround_kernel<<<XB, 256>>>(x, xr);
    preround_kernel<<<WB, 256>>>(wq, wr3);
    preround_kernel<<<WB, 256>>>(wk, wr3 + (size_t)D_ * D_);
    preround_kernel<<<WB, 256>>>(wv, wr3 + (size_t)2 * D_ * D_);

    // merged QKV projection: N = 6144
    gemm_tf32<1><<<dim3(6144 / 256, M_ / 128), 256, GEMM_SMEM>>>(
        xr, wr3, bq, bk, bv, q, k, v);

    rope_k_kernel<<<(B_ * H_ * S_ * 64) / 256, 256>>>();  // g_k -> g_xr (roped)

    attn_mma<<<dim3(S_ / 128, B_ * H_), 256, SMEM_ATTN>>>(ctx);

    preround_kernel<<<WB, 256>>>(wo, wr3);
    gemm_tf32<0><<<dim3(D_ / 256, M_ / 128), 256, GEMM_SMEM>>>(
        ctx, wr3, bo, bo, bo, out, out, out);
}

// round 15
// speedup vs baseline: 1.0806x; 1.0806x over previous
#include <cuda_runtime.h>
#include <math.h>
#include <stdint.h>

#define B_  4
#define S_  2048
#define D_  2048
#define H_  16
#define DH_ 128
#define M_  (B_*S_)

// Scratch (allowed: __device__ globals)
__device__ float g_q[(size_t)B_*H_*S_*DH_];    // Q [bh][s][dh]  (unroped)
__device__ float g_k[(size_t)B_*H_*S_*DH_];    // K [bh][s][dh]  (unroped)
__device__ float g_v[(size_t)B_*H_*S_*DH_];    // V [bh][dh][s]  (TRANSPOSED, tf32)
__device__ float g_ctx[(size_t)B_*S_*D_];
__device__ float g_xr[(size_t)M_*D_];          // tf32 x; later reused as roped-K
__device__ float g_wr3[(size_t)3*D_*D_];       // tf32 wq|wk|wv; wo reuses [0]
__device__ float g_cos[(size_t)S_*64];
__device__ float g_sin[(size_t)S_*64];

// ---------------------------------------------------------------------------
// Helpers
// ---------------------------------------------------------------------------
__device__ __forceinline__ uint32_t tf32u(float x) {
    uint32_t r;
    asm("cvt.rna.tf32.f32 %0, %1;" : "=r"(r) : "f"(x));
    return r;
}
__device__ __forceinline__ float f2tf32(float x) { return __uint_as_float(tf32u(x)); }

__device__ __forceinline__ void mma_tf32(float c[4], const uint32_t a[4], const uint32_t b[2]) {
    asm volatile(
        "mma.sync.aligned.m16n8k8.row.col.f32.tf32.tf32.f32 "
        "{%0,%1,%2,%3}, {%4,%5,%6,%7}, {%8,%9}, {%0,%1,%2,%3};"
        : "+f"(c[0]), "+f"(c[1]), "+f"(c[2]), "+f"(c[3])
        : "r"(a[0]), "r"(a[1]), "r"(a[2]), "r"(a[3]), "r"(b[0]), "r"(b[1]));
}

__device__ __forceinline__ void cp16(uint32_t dst, const void* src) {
    asm volatile("cp.async.cg.shared.global [%0], [%1], 16;" :: "r"(dst), "l"(src));
}

// ---------------------------------------------------------------------------
// Pre-round: out[i] = tf32(in[i])
// ---------------------------------------------------------------------------
__global__ __launch_bounds__(256)
void preround_kernel(const float* __restrict__ in, float* __restrict__ out)
{
    const int i = blockIdx.x * blockDim.x + threadIdx.x;
    float4 v = ((const float4*)in)[i];
    v.x = f2tf32(v.x); v.y = f2tf32(v.y);
    v.z = f2tf32(v.z); v.w = f2tf32(v.w);
    ((float4*)out)[i] = v;
}

// ---------------------------------------------------------------------------
// TF32 GEMM (R12-proven shape): 128x128 CTA, 128 threads (2x2 warps, 64x64
// warp tile), BK=32, 2-stage cp.async, stride-36 smem rows, 2 CTAs/SM.
// OUT=0: flat C0 = A·Wᵀ + b0.
// OUT=1: merged QKV (N=6144): which = n0>>11 selects dest/bias;
//        q,k -> heads [bh][s][dh]; v -> transposed [bh][dh][s] + tf32.
// ---------------------------------------------------------------------------
#define GBK 32

template<int OUT>
__global__ __launch_bounds__(128)
void gemm_tf32(const float* __restrict__ A, const float* __restrict__ W,
               const float* __restrict__ b0, const float* __restrict__ b1,
               const float* __restrict__ b2,
               float* __restrict__ C0, float* __restrict__ C1, float* __restrict__ C2)
{
    __shared__ float As[2][128][36];
    __shared__ float Ws[2][128][36];
    const int K  = D_;
    const int m0 = blockIdx.y * 128;
    const int n0 = blockIdx.x * 128;
    const int tid  = threadIdx.x;
    const int warp = tid >> 5, lane = tid & 31;
    const int wy = warp >> 1, wx = warp & 1;
    const int lr = lane >> 2, lc = lane & 3;

    float acc[4][8][4];
#pragma unroll
    for (int ti = 0; ti < 4; ti++)
#pragma unroll
        for (int nt = 0; nt < 8; nt++)
#pragma unroll
            for (int e = 0; e < 4; e++) acc[ti][nt][e] = 0.f;

    auto issue = [&](int st, int k0) {
#pragma unroll
        for (int u = 0; u < 8; u++) {
            const int f = tid + u * 128;
            const int r = f >> 3, c4 = f & 7;
            cp16((uint32_t)__cvta_generic_to_shared(&As[st][r][c4 * 4]),
                 A + (size_t)(m0 + r) * K + k0 + c4 * 4);
        }
#pragma unroll
        for (int u = 0; u < 8; u++) {
            const int f = tid + u * 128;
            const int r = f >> 3, c4 = f & 7;
            cp16((uint32_t)__cvta_generic_to_shared(&Ws[st][r][c4 * 4]),
                 W + (size_t)(n0 + r) * K + k0 + c4 * 4);
        }
        asm volatile("cp.async.commit_group;");
    };

    issue(0, 0);

    const int NIT = K / GBK;                    // 64
#pragma unroll 1
    for (int it = 0; it < NIT; it++) {
        asm volatile("cp.async.wait_group 0;");
        __syncthreads();
        if (it + 1 < NIT) issue((it + 1) & 1, (it + 1) * GBK);
        const int cur = it & 1;

#pragma unroll
        for (int kk = 0; kk < GBK; kk += 8) {
            uint32_t afr[4][4], bfr[8][2];
            const int ac = kk + lc;
#pragma unroll
            for (int ti = 0; ti < 4; ti++) {
                const int ar = wy * 64 + ti * 16 + lr;
                afr[ti][0] = __float_as_uint(As[cur][ar    ][ac]);
                afr[ti][1] = __float_as_uint(As[cur][ar + 8][ac]);
                afr[ti][2] = __float_as_uint(As[cur][ar    ][ac + 4]);
                afr[ti][3] = __float_as_uint(As[cur][ar + 8][ac + 4]);
            }
#pragma unroll
            for (int nt = 0; nt < 8; nt++) {
                const int br = wx * 64 + nt * 8 + lr;
                bfr[nt][0] = __float_as_uint(Ws[cur][br][ac]);
                bfr[nt][1] = __float_as_uint(Ws[cur][br][ac + 4]);
            }
#pragma unroll
            for (int ti = 0; ti < 4; ti++)
#pragma unroll
                for (int nt = 0; nt < 8; nt++)
                    mma_tf32(acc[ti][nt], afr[ti], bfr[nt]);
        }
    }

    // ---- epilogue: CTA lies entirely in one 2048-col segment for OUT=1 ----
    const int which = n0 >> 11;                       // 0=q, 1=k, 2=v
    const float* bias = (OUT == 1) ? (which == 0 ? b0 : which == 1 ? b1 : b2) : b0;
    float* Cqk = (which == 0) ? C0 : C1;

#pragma unroll
    for (int ti = 0; ti < 4; ti++) {
#pragma unroll
        for (int nt = 0; nt < 8; nt++) {
            const int row = m0 + wy * 64 + ti * 16 + lr;
            const int col = n0 + wx * 64 + nt * 8 + lc * 2;
#pragma unroll
            for (int e = 0; e < 4; e++) {
                const int m = row + (e >> 1) * 8;
                const int n = col + (e & 1);
                const int nn = n & 2047;
                const float v = acc[ti][nt][e] + bias[OUT == 1 ? nn : n];
                if (OUT == 1) {
                    const int bb = m >> 11, s = m & (S_ - 1);
                    const int h = nn >> 7, dh = nn & 127;
                    if (which == 2)
                        C2[(((size_t)(bb * H_ + h)) * DH_ + dh) * S_ + s] = f2tf32(v);
                    else
                        Cqk[(((size_t)bb * H_ + h) * S_ + s) * DH_ + dh] = v;
                } else {
                    C0[(size_t)m * D_ + n] = v;
                }
            }
        }
    }
}

// ---------------------------------------------------------------------------
// RoPE table + K pre-rope (roped, tf32, into g_xr)
// ---------------------------------------------------------------------------
__global__ __launch_bounds__(256)
void rope_table_kernel()
{
    const int idx = blockIdx.x * blockDim.x + threadIdx.x;
    const int p = idx & 63;
    const int s = idx >> 6;
    const float invf = (float)exp(-(double)p * (log(10000.0) / 64.0));
    const float ang  = (float)s * invf;
    g_cos[idx] = (float)cos((double)ang);
    g_sin[idx] = (float)sin((double)ang);
}

__global__ __launch_bounds__(256)
void rope_k_kernel()
{
    const int idx = blockIdx.x * blockDim.x + threadIdx.x;  // B*H*S*64
    const int p   = idx & 63;
    const int row = idx >> 6;
    const int s   = row & (S_ - 1);
    const float cs = g_cos[s * 64 + p];
    const float sn = g_sin[s * 64 + p];
    const float* kb = g_k + (size_t)row * DH_;
    float* kr = g_xr + (size_t)row * DH_;
    const float k1 = kb[p], k2 = kb[p + 64];
    kr[p]      = f2tf32(k1 * cs - k2 * sn);
    kr[p + 64] = f2tf32(k2 * cs + k1 * sn);
}

// ---------------------------------------------------------------------------
// TF32 flash attention v3 (R11/R12-proven): 256 threads / 8 warps,
// 128 q-rows/CTA, 64-key KV tiles double-buffered via cp.async.
// ---------------------------------------------------------------------------
#define KPAD 132
#define VPAD 68
#define PPAD 76
#define SMEM_ATTN ((128*KPAD + 2*128*VPAD + 128*PPAD) * 4)

__global__ __launch_bounds__(256)
void attn_mma(float* __restrict__ ctx)
{
    extern __shared__ float sm[];
    float* KB = sm;                        // 128*KPAD (2 x 64-row buffers)
    float* VB = sm + 128 * KPAD;           // 2 x 128*VPAD
    float* Ps = VB + 2 * 128 * VPAD;       // 128*PPAD

    const int bh  = blockIdx.y;
    const int m0  = blockIdx.x * 128;
    const int tid = threadIdx.x;
    const int warp = tid >> 5, lane = tid & 31;
    const int lr = lane >> 2, lc = lane & 3;
    const int qr = warp * 16;

    const float* Qb = g_q  + (size_t)bh * S_ * DH_;
    const float* Kr = g_xr + (size_t)bh * S_ * DH_;       // roped, tf32
    const float* Vt = g_v  + (size_t)bh * DH_ * S_;       // [dh][s], tf32

    const float scale = 0.08838834764831845f;   // 1/sqrt(128)

    // ---- stage Q with fused rope, scaled, tf32, into KB ----
#pragma unroll
    for (int i = 0; i < 8; i++) {
        const int idx = tid + i * 256;      // 128 rows x 16 pair-chunks
        const int r  = idx >> 4;
        const int p4 = idx & 15;
        const int s  = m0 + r;
        const float4 v1 = *(const float4*)(Qb + (size_t)s * DH_ + p4 * 4);
        const float4 v2 = *(const float4*)(Qb + (size_t)s * DH_ + p4 * 4 + 64);
        const float4 cs = *(const float4*)(g_cos + s * 64 + p4 * 4);
        const float4 sn = *(const float4*)(g_sin + s * 64 + p4 * 4);
        float4 o1, o2;
        o1.x = f2tf32((v1.x * cs.x - v2.x * sn.x) * scale);
        o1.y = f2tf32((v1.y * cs.y - v2.y * sn.y) * scale);
        o1.z = f2tf32((v1.z * cs.z - v2.z * sn.z) * scale);
        o1.w = f2tf32((v1.w * cs.w - v2.w * sn.w) * scale);
        o2.x = f2tf32((v2.x * cs.x + v1.x * sn.x) * scale);
        o2.y = f2tf32((v2.y * cs.y + v1.y * sn.y) * scale);
        o2.z = f2tf32((v2.z * cs.z + v1.z * sn.z) * scale);
        o2.w = f2tf32((v2.w * cs.w + v1.w * sn.w) * scale);
        *(float4*)(&KB[r * KPAD + p4 * 4])      = o1;
        *(float4*)(&KB[r * KPAD + p4 * 4 + 64]) = o2;
    }
    __syncthreads();
    uint32_t qf[16][4];
#pragma unroll
    for (int ks = 0; ks < 16; ks++) {
        qf[ks][0] = __float_as_uint(KB[(qr + lr    ) * KPAD + ks * 8 + lc    ]);
        qf[ks][1] = __float_as_uint(KB[(qr + lr + 8) * KPAD + ks * 8 + lc    ]);
        qf[ks][2] = __float_as_uint(KB[(qr + lr    ) * KPAD + ks * 8 + lc + 4]);
        qf[ks][3] = __float_as_uint(KB[(qr + lr + 8) * KPAD + ks * 8 + lc + 4]);
    }
    __syncthreads();   // Q fully consumed before K tiles overwrite KB

    auto issue_tile = [&](int t) {
        const int buf = t & 1;
        const int key0 = t * 64;
        float* kb = KB + buf * 64 * KPAD;
        float* vb = VB + buf * 128 * VPAD;
#pragma unroll
        for (int u = 0; u < 8; u++) {
            const int c = tid + u * 256;
            const int r = c >> 5, c4 = c & 31;
            cp16((uint32_t)__cvta_generic_to_shared(&kb[r * KPAD + c4 * 4]),
                 Kr + (size_t)(key0 + r) * DH_ + c4 * 4);
        }
#pragma unroll
        for (int u = 0; u < 8; u++) {
            const int c = tid + u * 256;
            const int r = c >> 4, c4 = c & 15;
            cp16((uint32_t)__cvta_generic_to_shared(&vb[r * VPAD + c4 * 4]),
                 Vt + (size_t)r * S_ + key0 + c4 * 4);
        }
        asm volatile("cp.async.commit_group;");
    };

    issue_tile(0);
    issue_tile(1);

    float oacc[16][4];
#pragma unroll
    for (int nt = 0; nt < 16; nt++)
#pragma unroll
        for (int e = 0; e < 4; e++) oacc[nt][e] = 0.f;
    float mr0 = -1e30f, mr1 = -1e30f, lsum0 = 0.f, lsum1 = 0.f;

#pragma unroll 1
    for (int kt = 0; kt < 32; kt++) {
        asm volatile("cp.async.wait_group %0;" :: "n"(1));
        __syncthreads();
        const int buf = kt & 1;
        const float* kb = KB + buf * 64 * KPAD;
        const float* vb = VB + buf * 128 * VPAD;

        float sacc[8][4];
#pragma unroll
        for (int n = 0; n < 8; n++)
#pragma unroll
            for (int e = 0; e < 4; e++) sacc[n][e] = 0.f;
#pragma unroll
        for (int ks = 0; ks < 16; ks++) {
#pragma unroll
            for (int n = 0; n < 8; n++) {
                uint32_t b[2];
                b[0] = __float_as_uint(kb[(n * 8 + lr) * KPAD + ks * 8 + lc    ]);
                b[1] = __float_as_uint(kb[(n * 8 + lr) * KPAD + ks * 8 + lc + 4]);
                mma_tf32(sacc[n], qf[ks], b);
            }
        }

        float mx0 = mr0, mx1 = mr1;
#pragma unroll
        for (int n = 0; n < 8; n++) {
            mx0 = fmaxf(mx0, fmaxf(sacc[n][0], sacc[n][1]));
            mx1 = fmaxf(mx1, fmaxf(sacc[n][2], sacc[n][3]));
        }
        mx0 = fmaxf(mx0, __shfl_xor_sync(0xffffffffu, mx0, 1));
        mx0 = fmaxf(mx0, __shfl_xor_sync(0xffffffffu, mx0, 2));
        mx1 = fmaxf(mx1, __shfl_xor_sync(0xffffffffu, mx1, 1));
        mx1 = fmaxf(mx1, __shfl_xor_sync(0xffffffffu, mx1, 2));
        const float f0 = __expf(mr0 - mx0);
        const float f1 = __expf(mr1 - mx1);
        mr0 = mx0; mr1 = mx1;

        float s0 = 0.f, s1 = 0.f;
#pragma unroll
        for (int n = 0; n < 8; n++) {
            const float p0 = __expf(sacc[n][0] - mx0);
            const float p1 = __expf(sacc[n][1] - mx0);
            const float p2 = __expf(sacc[n][2] - mx1);
            const float p3 = __expf(sacc[n][3] - mx1);
            s0 += p0 + p1; s1 += p2 + p3;
            float2 lo; lo.x = f2tf32(p0); lo.y = f2tf32(p1);
            *(float2*)(&Ps[(qr + lr    ) * PPAD + n * 8 + lc * 2]) = lo;
            float2 hi; hi.x = f2tf32(p2); hi.y = f2tf32(p3);
            *(float2*)(&Ps[(qr + lr + 8) * PPAD + n * 8 + lc * 2]) = hi;
        }
        s0 += __shfl_xor_sync(0xffffffffu, s0, 1);
        s0 += __shfl_xor_sync(0xffffffffu, s0, 2);
        s1 += __shfl_xor_sync(0xffffffffu, s1, 1);
        s1 += __shfl_xor_sync(0xffffffffu, s1, 2);
        lsum0 = lsum0 * f0 + s0;
        lsum1 = lsum1 * f1 + s1;
#pragma unroll
        for (int nt = 0; nt < 16; nt++) {
            oacc[nt][0] *= f0; oacc[nt][1] *= f0;
            oacc[nt][2] *= f1; oacc[nt][3] *= f1;
        }
        __syncwarp();

#pragma unroll
        for (int kk = 0; kk < 8; kk++) {
            uint32_t af[4];
            af[0] = __float_as_uint(Ps[(qr + lr    ) * PPAD + kk * 8 + lc    ]);
            af[1] = __float_as_uint(Ps[(qr + lr + 8) * PPAD + kk * 8 + lc    ]);
            af[2] = __float_as_uint(Ps[(qr + lr    ) * PPAD + kk * 8 + lc + 4]);
            af[3] = __float_as_uint(Ps[(qr + lr + 8) * PPAD + kk * 8 + lc + 4]);
#pragma unroll
            for (int nt = 0; nt < 16; nt++) {
                uint32_t b[2];
                b[0] = __float_as_uint(vb[(nt * 8 + lr) * VPAD + kk * 8 + lc    ]);
                b[1] = __float_as_uint(vb[(nt * 8 + lr) * VPAD + kk * 8 + lc + 4]);
                mma_tf32(oacc[nt], af, b);
            }
        }

        __syncthreads();
        if (kt + 2 < 32) {
            issue_tile(kt + 2);
        } else {
            asm volatile("cp.async.commit_group;");
        }
    }

    const float i0 = 1.f / lsum0, i1 = 1.f / lsum1;
    const int bb = bh >> 4, h = bh & 15;
    const int gr0 = m0 + qr + lr;
    float* o0 = ctx + ((size_t)bb * S_ + gr0) * D_ + h * DH_;
    float* o1 = o0 + (size_t)8 * D_;
#pragma unroll
    for (int nt = 0; nt < 16; nt++) {
        float2 a; a.x = f2tf32(oacc[nt][0] * i0); a.y = f2tf32(oacc[nt][1] * i0);
        *(float2*)(o0 + nt * 8 + lc * 2) = a;
        float2 b; b.x = f2tf32(oacc[nt][2] * i1); b.y = f2tf32(oacc[nt][3] * i1);
        *(float2*)(o1 + nt * 8 + lc * 2) = b;
    }
}

// ---------------------------------------------------------------------------
extern "C" void kernel_launch(void* const* d_in, const int* in_sizes, int n_in,
                              void* d_out, int out_size)
{
    const float* x  = (const float*)d_in[0];
    const float* wq = (const float*)d_in[1];
    const float* bq = (const float*)d_in[2];
    const float* wk = (const float*)d_in[3];
    const float* bk = (const float*)d_in[4];
    const float* wv = (const float*)d_in[5];
    const float* bv = (const float*)d_in[6];
    const float* wo = (const float*)d_in[7];
    const float* bo = (const float*)d_in[8];
    float* out = (float*)d_out;

    float *q, *k, *v, *ctx, *xr, *wr3;
    cudaGetSymbolAddress((void**)&q,   g_q);
    cudaGetSymbolAddress((void**)&k,   g_k);
    cudaGetSymbolAddress((void**)&v,   g_v);
    cudaGetSymbolAddress((void**)&ctx, g_ctx);
    cudaGetSymbolAddress((void**)&xr,  g_xr);
    cudaGetSymbolAddress((void**)&wr3, g_wr3);

    cudaFuncSetAttribute(attn_mma, cudaFuncAttributeMaxDynamicSharedMemorySize, SMEM_ATTN);

    const int XB = (M_ * D_) / 4 / 256;
    const int WB = (D_ * D_) / 4 / 256;

    rope_table_kernel<<<(S_ * 64) / 256, 256>>>();
    preround_kernel<<<XB, 256>>>(x, xr);
    preround_kernel<<<WB, 256>>>(wq, wr3);
    preround_kernel<<<WB, 256>>>(wk, wr3 + (size_t)D_ * D_);
    preround_kernel<<<WB, 256>>>(wv, wr3 + (size_t)2 * D_ * D_);

    // merged QKV projection: N = 6144, 128-col CTA tiles
    gemm_tf32<1><<<dim3(6144 / 128, M_ / 128), 128>>>(
        xr, wr3, bq, bk, bv, q, k, v);

    rope_k_kernel<<<(B_ * H_ * S_ * 64) / 256, 256>>>();  // g_k -> g_xr (roped)

    attn_mma<<<dim3(S_ / 128, B_ * H_), 256, SMEM_ATTN>>>(ctx);

    preround_kernel<<<WB, 256>>>(wo, wr3);
    gemm_tf32<0><<<dim3(D_ / 128, M_ / 128), 128>>>(
        ctx, wr3, bo, bo, bo, out, out, out);
}

// round 16
// speedup vs baseline: 1.8434x; 1.7059x over previous
#include <cuda_runtime.h>
#include <cuda_fp16.h>
#include <math.h>
#include <stdint.h>

#define B_  4
#define S_  2048
#define D_  2048
#define H_  16
#define DH_ 128
#define M_  (B_*S_)

// Scratch (allowed: __device__ globals)
__device__ float  g_q[(size_t)B_*H_*S_*DH_];    // Q [bh][s][dh] f32 (unroped)
__device__ float  g_k[(size_t)B_*H_*S_*DH_];    // K [bh][s][dh] f32 (unroped)
__device__ __half g_kh[(size_t)B_*H_*S_*DH_];   // K roped, fp16
__device__ __half g_vh[(size_t)B_*H_*DH_*S_];   // V transposed [bh][dh][s], fp16
__device__ __half g_ctxh[(size_t)B_*S_*D_];     // ctx fp16
__device__ __half g_xh[(size_t)M_*D_];          // x fp16
__device__ __half g_w3h[(size_t)3*D_*D_];       // wq|wk|wv fp16; wo reuses [0]
__device__ float  g_cos[(size_t)S_*64];
__device__ float  g_sin[(size_t)S_*64];

// ---------------------------------------------------------------------------
// Helpers
// ---------------------------------------------------------------------------
__device__ __forceinline__ uint32_t f22h2(float a, float b) {
    __half2 h = __floats2half2_rn(a, b);
    return *reinterpret_cast<uint32_t*>(&h);
}

__device__ __forceinline__ void mma_f16(float c[4], const uint32_t a[4], const uint32_t b[2]) {
    asm volatile(
        "mma.sync.aligned.m16n8k16.row.col.f32.f16.f16.f32 "
        "{%0,%1,%2,%3}, {%4,%5,%6,%7}, {%8,%9}, {%0,%1,%2,%3};"
        : "+f"(c[0]), "+f"(c[1]), "+f"(c[2]), "+f"(c[3])
        : "r"(a[0]), "r"(a[1]), "r"(a[2]), "r"(a[3]), "r"(b[0]), "r"(b[1]));
}

__device__ __forceinline__ void cp16(uint32_t dst, const void* src) {
    asm volatile("cp.async.cg.shared.global [%0], [%1], 16;" :: "r"(dst), "l"(src));
}

// ---------------------------------------------------------------------------
// f32 -> fp16 convert (4 elems/thread)
// ---------------------------------------------------------------------------
__global__ __launch_bounds__(256)
void tohalf_kernel(const float* __restrict__ in, __half* __restrict__ out)
{
    const int i = blockIdx.x * blockDim.x + threadIdx.x;
    float4 v = ((const float4*)in)[i];
    uint2 o;
    o.x = f22h2(v.x, v.y);
    o.y = f22h2(v.z, v.w);
    ((uint2*)out)[i] = o;
}

// ---------------------------------------------------------------------------
// FP16 GEMM: 128x128 CTA, 128 threads (2x2 warps, 64x64 warp tile), BK=32,
// 2-stage cp.async, smem as half2-packed u32 stride 20 (conflict-free).
// OUT=0: flat f32 C0 = A·Wᵀ + b0.
// OUT=1: merged QKV (N=6144): which = n0>>11; q,k -> f32 heads [bh][s][dh];
//        v -> fp16 transposed [bh][dh][s].
// ---------------------------------------------------------------------------
#define GBK 32

template<int OUT>
__global__ __launch_bounds__(128)
void gemm_f16(const __half* __restrict__ A, const __half* __restrict__ W,
              const float* __restrict__ b0, const float* __restrict__ b1,
              const float* __restrict__ b2,
              float* __restrict__ C0, float* __restrict__ C1,
              __half* __restrict__ C2)
{
    __shared__ uint32_t As[2][128][20];   // [stage][row][16 u32 = 32 halves + pad]
    __shared__ uint32_t Ws[2][128][20];
    const int K  = D_;
    const int m0 = blockIdx.y * 128;
    const int n0 = blockIdx.x * 128;
    const int tid  = threadIdx.x;
    const int warp = tid >> 5, lane = tid & 31;
    const int wy = warp >> 1, wx = warp & 1;
    const int lr = lane >> 2, lc = lane & 3;

    float acc[4][8][4];
#pragma unroll
    for (int ti = 0; ti < 4; ti++)
#pragma unroll
        for (int nt = 0; nt < 8; nt++)
#pragma unroll
            for (int e = 0; e < 4; e++) acc[ti][nt][e] = 0.f;

    auto issue = [&](int st, int k0) {
#pragma unroll
        for (int u = 0; u < 4; u++) {     // 512 chunks of 16B (8 halves)
            const int f = tid + u * 128;
            const int r = f >> 2, c = f & 3;
            cp16((uint32_t)__cvta_generic_to_shared(&As[st][r][c * 4]),
                 A + (size_t)(m0 + r) * K + k0 + c * 8);
        }
#pragma unroll
        for (int u = 0; u < 4; u++) {
            const int f = tid + u * 128;
            const int r = f >> 2, c = f & 3;
            cp16((uint32_t)__cvta_generic_to_shared(&Ws[st][r][c * 4]),
                 W + (size_t)(n0 + r) * K + k0 + c * 8);
        }
        asm volatile("cp.async.commit_group;");
    };

    issue(0, 0);

    const int NIT = K / GBK;              // 64
#pragma unroll 1
    for (int it = 0; it < NIT; it++) {
        asm volatile("cp.async.wait_group 0;");
        __syncthreads();
        if (it + 1 < NIT) issue((it + 1) & 1, (it + 1) * GBK);
        const int cur = it & 1;

#pragma unroll
        for (int kk = 0; kk < 16; kk += 8) {    // two k16 steps (u32 cols)
            uint32_t afr[4][4], bfr[8][2];
            const int ac = kk + lc;
#pragma unroll
            for (int ti = 0; ti < 4; ti++) {
                const int ar = wy * 64 + ti * 16 + lr;
                afr[ti][0] = As[cur][ar    ][ac];
                afr[ti][1] = As[cur][ar + 8][ac];
                afr[ti][2] = As[cur][ar    ][ac + 4];
                afr[ti][3] = As[cur][ar + 8][ac + 4];
            }
#pragma unroll
            for (int nt = 0; nt < 8; nt++) {
                const int br = wx * 64 + nt * 8 + lr;
                bfr[nt][0] = Ws[cur][br][ac];
                bfr[nt][1] = Ws[cur][br][ac + 4];
            }
#pragma unroll
            for (int ti = 0; ti < 4; ti++)
#pragma unroll
                for (int nt = 0; nt < 8; nt++)
                    mma_f16(acc[ti][nt], afr[ti], bfr[nt]);
        }
    }

    // ---- epilogue: CTA lies entirely in one 2048-col segment for OUT=1 ----
    const int which = n0 >> 11;
    const float* bias = (OUT == 1) ? (which == 0 ? b0 : which == 1 ? b1 : b2) : b0;
    float* Cqk = (which == 0) ? C0 : C1;

#pragma unroll
    for (int ti = 0; ti < 4; ti++) {
#pragma unroll
        for (int nt = 0; nt < 8; nt++) {
            const int row = m0 + wy * 64 + ti * 16 + lr;
            const int col = n0 + wx * 64 + nt * 8 + lc * 2;
#pragma unroll
            for (int e = 0; e < 4; e++) {
                const int m = row + (e >> 1) * 8;
                const int n = col + (e & 1);
                const int nn = n & 2047;
                const float v = acc[ti][nt][e] + bias[OUT == 1 ? nn : n];
                if (OUT == 1) {
                    const int bb = m >> 11, s = m & (S_ - 1);
                    const int h = nn >> 7, dh = nn & 127;
                    if (which == 2)
                        C2[(((size_t)(bb * H_ + h)) * DH_ + dh) * S_ + s] = __float2half_rn(v);
                    else
                        Cqk[(((size_t)bb * H_ + h) * S_ + s) * DH_ + dh] = v;
                } else {
                    C0[(size_t)m * D_ + n] = v;
                }
            }
        }
    }
}

// ---------------------------------------------------------------------------
// RoPE table + K pre-rope (f32 math, fp16 output)
// ---------------------------------------------------------------------------
__global__ __launch_bounds__(256)
void rope_table_kernel()
{
    const int idx = blockIdx.x * blockDim.x + threadIdx.x;
    const int p = idx & 63;
    const int s = idx >> 6;
    const float invf = (float)exp(-(double)p * (log(10000.0) / 64.0));
    const float ang  = (float)s * invf;
    g_cos[idx] = (float)cos((double)ang);
    g_sin[idx] = (float)sin((double)ang);
}

__global__ __launch_bounds__(256)
void rope_k_kernel()
{
    const int idx = blockIdx.x * blockDim.x + threadIdx.x;  // B*H*S*64
    const int p   = idx & 63;
    const int row = idx >> 6;
    const int s   = row & (S_ - 1);
    const float cs = g_cos[s * 64 + p];
    const float sn = g_sin[s * 64 + p];
    const float* kb = g_k + (size_t)row * DH_;
    __half* kr = g_kh + (size_t)row * DH_;
    const float k1 = kb[p], k2 = kb[p + 64];
    kr[p]      = __float2half_rn(k1 * cs - k2 * sn);
    kr[p + 64] = __float2half_rn(k2 * cs + k1 * sn);
}

// ---------------------------------------------------------------------------
// FP16 flash attention: 256 threads / 8 warps, 128 q-rows/CTA (16/warp),
// 64-key KV tiles double-buffered via cp.async. Smem as half2 u32:
// KB stride 68, VB/Ps stride 36 (all conflict-free). 90KB -> 2 CTAs/SM.
// ---------------------------------------------------------------------------
#define KPADU 68
#define VPADU 36
#define PPADU 36
#define SMEM_ATTN ((128*KPADU + 2*128*VPADU + 128*PPADU) * 4)

__global__ __launch_bounds__(256)
void attn_f16()
{
    extern __shared__ uint32_t smu[];
    uint32_t* KB = smu;                         // Q staging 128 rows / 2x64-row K bufs
    uint32_t* VB = smu + 128 * KPADU;           // 2 x 128 x VPADU
    uint32_t* Ps = VB + 2 * 128 * VPADU;        // 128 x PPADU

    const int bh  = blockIdx.y;
    const int m0  = blockIdx.x * 128;
    const int tid = threadIdx.x;
    const int warp = tid >> 5, lane = tid & 31;
    const int lr = lane >> 2, lc = lane & 3;
    const int qr = warp * 16;

    const float*  Qb = g_q  + (size_t)bh * S_ * DH_;
    const __half* Kh = g_kh + (size_t)bh * S_ * DH_;
    const __half* Vh = g_vh + (size_t)bh * DH_ * S_;

    const float scale = 0.08838834764831845f;   // 1/sqrt(128)

    // ---- stage Q with fused rope, scaled, fp16, into KB ----
#pragma unroll
    for (int i = 0; i < 8; i++) {
        const int idx = tid + i * 256;          // 128 rows x 16 pair-chunks
        const int r  = idx >> 4;
        const int p4 = idx & 15;
        const int s  = m0 + r;
        const float4 v1 = *(const float4*)(Qb + (size_t)s * DH_ + p4 * 4);
        const float4 v2 = *(const float4*)(Qb + (size_t)s * DH_ + p4 * 4 + 64);
        const float4 cs = *(const float4*)(g_cos + s * 64 + p4 * 4);
        const float4 sn = *(const float4*)(g_sin + s * 64 + p4 * 4);
        uint2 lo, hi;
        lo.x = f22h2((v1.x * cs.x - v2.x * sn.x) * scale,
                     (v1.y * cs.y - v2.y * sn.y) * scale);
        lo.y = f22h2((v1.z * cs.z - v2.z * sn.z) * scale,
                     (v1.w * cs.w - v2.w * sn.w) * scale);
        hi.x = f22h2((v2.x * cs.x + v1.x * sn.x) * scale,
                     (v2.y * cs.y + v1.y * sn.y) * scale);
        hi.y = f22h2((v2.z * cs.z + v1.z * sn.z) * scale,
                     (v2.w * cs.w + v1.w * sn.w) * scale);
        *(uint2*)(&KB[r * KPADU + p4 * 2])      = lo;   // halves d = p4*4..+3
        *(uint2*)(&KB[r * KPADU + 32 + p4 * 2]) = hi;   // halves d = 64+p4*4..+3
    }
    __syncthreads();
    uint32_t qf[8][4];
#pragma unroll
    for (int ks = 0; ks < 8; ks++) {            // 8 k16 steps over DH=128
        const int ac = ks * 8 + lc;
        qf[ks][0] = KB[(qr + lr    ) * KPADU + ac];
        qf[ks][1] = KB[(qr + lr + 8) * KPADU + ac];
        qf[ks][2] = KB[(qr + lr    ) * KPADU + ac + 4];
        qf[ks][3] = KB[(qr + lr + 8) * KPADU + ac + 4];
    }
    __syncthreads();   // Q consumed before K tiles overwrite KB

    auto issue_tile = [&](int t) {
        const int buf = t & 1;
        const int key0 = t * 64;
        uint32_t* kb = KB + buf * 64 * KPADU;
        uint32_t* vb = VB + buf * 128 * VPADU;
#pragma unroll
        for (int u = 0; u < 4; u++) {           // K: 64 rows x 16 chunks
            const int c = tid + u * 256;
            const int r = c >> 4, c8 = c & 15;
            cp16((uint32_t)__cvta_generic_to_shared(&kb[r * KPADU + c8 * 4]),
                 Kh + (size_t)(key0 + r) * DH_ + c8 * 8);
        }
#pragma unroll
        for (int u = 0; u < 4; u++) {           // V: 128 rows x 8 chunks
            const int c = tid + u * 256;
            const int r = c >> 3, c8 = c & 7;
            cp16((uint32_t)__cvta_generic_to_shared(&vb[r * VPADU + c8 * 4]),
                 Vh + (size_t)r * S_ + key0 + c8 * 8);
        }
        asm volatile("cp.async.commit_group;");
    };

    issue_tile(0);
    issue_tile(1);

    float oacc[16][4];
#pragma unroll
    for (int nt = 0; nt < 16; nt++)
#pragma unroll
        for (int e = 0; e < 4; e++) oacc[nt][e] = 0.f;
    float mr0 = -1e30f, mr1 = -1e30f, lsum0 = 0.f, lsum1 = 0.f;

#pragma unroll 1
    for (int kt = 0; kt < 32; kt++) {
        asm volatile("cp.async.wait_group %0;" :: "n"(1));
        __syncthreads();
        const int buf = kt & 1;
        const uint32_t* kb = KB + buf * 64 * KPADU;
        const uint32_t* vb = VB + buf * 128 * VPADU;

        // ---- S = Q·Kᵀ ----
        float sacc[8][4];
#pragma unroll
        for (int n = 0; n < 8; n++)
#pragma unroll
            for (int e = 0; e < 4; e++) sacc[n][e] = 0.f;
#pragma unroll
        for (int ks = 0; ks < 8; ks++) {
            const int ac = ks * 8 + lc;
#pragma unroll
            for (int n = 0; n < 8; n++) {
                uint32_t b[2];
                b[0] = kb[(n * 8 + lr) * KPADU + ac];
                b[1] = kb[(n * 8 + lr) * KPADU + ac + 4];
                mma_f16(sacc[n], qf[ks], b);
            }
        }

        // ---- online softmax ----
        float mx0 = mr0, mx1 = mr1;
#pragma unroll
        for (int n = 0; n < 8; n++) {
            mx0 = fmaxf(mx0, fmaxf(sacc[n][0], sacc[n][1]));
            mx1 = fmaxf(mx1, fmaxf(sacc[n][2], sacc[n][3]));
        }
        mx0 = fmaxf(mx0, __shfl_xor_sync(0xffffffffu, mx0, 1));
        mx0 = fmaxf(mx0, __shfl_xor_sync(0xffffffffu, mx0, 2));
        mx1 = fmaxf(mx1, __shfl_xor_sync(0xffffffffu, mx1, 1));
        mx1 = fmaxf(mx1, __shfl_xor_sync(0xffffffffu, mx1, 2));
        const float f0 = __expf(mr0 - mx0);
        const float f1 = __expf(mr1 - mx1);
        mr0 = mx0; mr1 = mx1;

        float s0 = 0.f, s1 = 0.f;
#pragma unroll
        for (int n = 0; n < 8; n++) {
            const float p0 = __expf(sacc[n][0] - mx0);
            const float p1 = __expf(sacc[n][1] - mx0);
            const float p2 = __expf(sacc[n][2] - mx1);
            const float p3 = __expf(sacc[n][3] - mx1);
            s0 += p0 + p1; s1 += p2 + p3;
            Ps[(qr + lr    ) * PPADU + n * 4 + lc] = f22h2(p0, p1);
            Ps[(qr + lr + 8) * PPADU + n * 4 + lc] = f22h2(p2, p3);
        }
        s0 += __shfl_xor_sync(0xffffffffu, s0, 1);
        s0 += __shfl_xor_sync(0xffffffffu, s0, 2);
        s1 += __shfl_xor_sync(0xffffffffu, s1, 1);
        s1 += __shfl_xor_sync(0xffffffffu, s1, 2);
        lsum0 = lsum0 * f0 + s0;
        lsum1 = lsum1 * f1 + s1;
#pragma unroll
        for (int nt = 0; nt < 16; nt++) {
            oacc[nt][0] *= f0; oacc[nt][1] *= f0;
            oacc[nt][2] *= f1; oacc[nt][3] *= f1;
        }
        __syncwarp();  // own-warp P stores before P fragment loads

        // ---- O += P·V ----
#pragma unroll
        for (int kk = 0; kk < 4; kk++) {        // 4 k16 steps over 64 keys
            const int ac = kk * 8 + lc;
            uint32_t af[4];
            af[0] = Ps[(qr + lr    ) * PPADU + ac];
            af[1] = Ps[(qr + lr + 8) * PPADU + ac];
            af[2] = Ps[(qr + lr    ) * PPADU + ac + 4];
            af[3] = Ps[(qr + lr + 8) * PPADU + ac + 4];
#pragma unroll
            for (int nt = 0; nt < 16; nt++) {
                uint32_t b[2];
                b[0] = vb[(nt * 8 + lr) * VPADU + ac];
                b[1] = vb[(nt * 8 + lr) * VPADU + ac + 4];
                mma_f16(oacc[nt], af, b);
            }
        }

        __syncthreads();
        if (kt + 2 < 32) {
            issue_tile(kt + 2);
        } else {
            asm volatile("cp.async.commit_group;");
        }
    }

    // ---- epilogue: normalize, fp16 ctx (final GEMM consumes directly) ----
    const float i0 = 1.f / lsum0, i1 = 1.f / lsum1;
    const int bb = bh >> 4, h = bh & 15;
    const int gr0 = m0 + qr + lr;
    uint32_t* ctxu = (uint32_t*)g_ctxh;
    uint32_t* o0 = ctxu + ((size_t)bb * S_ + gr0) * (D_ / 2) + h * 64;
    uint32_t* o1 = o0 + (size_t)8 * (D_ / 2);
#pragma unroll
    for (int nt = 0; nt < 16; nt++) {
        o0[nt * 4 + lc] = f22h2(oacc[nt][0] * i0, oacc[nt][1] * i0);
        o1[nt * 4 + lc] = f22h2(oacc[nt][2] * i1, oacc[nt][3] * i1);
    }
}

// ---------------------------------------------------------------------------
extern "C" void kernel_launch(void* const* d_in, const int* in_sizes, int n_in,
                              void* d_out, int out_size)
{
    const float* x  = (const float*)d_in[0];
    const float* wq = (const float*)d_in[1];
    const float* bq = (const float*)d_in[2];
    const float* wk = (const float*)d_in[3];
    const float* bk = (const float*)d_in[4];
    const float* wv = (const float*)d_in[5];
    const float* bv = (const float*)d_in[6];
    const float* wo = (const float*)d_in[7];
    const float* bo = (const float*)d_in[8];
    float* out = (float*)d_out;

    float  *q, *k;
    __half *kh, *vh, *ctxh, *xh, *w3h;
    cudaGetSymbolAddress((void**)&q,    g_q);
    cudaGetSymbolAddress((void**)&k,    g_k);
    cudaGetSymbolAddress((void**)&kh,   g_kh);
    cudaGetSymbolAddress((void**)&vh,   g_vh);
    cudaGetSymbolAddress((void**)&ctxh, g_ctxh);
    cudaGetSymbolAddress((void**)&xh,   g_xh);
    cudaGetSymbolAddress((void**)&w3h,  g_w3h);

    cudaFuncSetAttribute(attn_f16, cudaFuncAttributeMaxDynamicSharedMemorySize, SMEM_ATTN);

    const int XB = (M_ * D_) / 4 / 256;
    const int WB = (D_ * D_) / 4 / 256;

    rope_table_kernel<<<(S_ * 64) / 256, 256>>>();
    tohalf_kernel<<<XB, 256>>>(x, xh);
    tohalf_kernel<<<WB, 256>>>(wq, w3h);
    tohalf_kernel<<<WB, 256>>>(wk, w3h + (size_t)D_ * D_);
    tohalf_kernel<<<WB, 256>>>(wv, w3h + (size_t)2 * D_ * D_);

    // merged QKV projection: N = 6144
    gemm_f16<1><<<dim3(6144 / 128, M_ / 128), 128>>>(
        xh, w3h, bq, bk, bv, q, k, vh);

    rope_k_kernel<<<(B_ * H_ * S_ * 64) / 256, 256>>>();  // g_k -> g_kh roped

    attn_f16<<<dim3(S_ / 128, B_ * H_), 256, SMEM_ATTN>>>();

    tohalf_kernel<<<WB, 256>>>(wo, w3h);
    gemm_f16<0><<<dim3(D_ / 128, M_ / 128), 128>>>(
        ctxh, w3h, bo, bo, bo, out, out, (__half*)nullptr);
}

// round 17
// speedup vs baseline: 1.9732x; 1.0704x over previous
#include <cuda_runtime.h>
#include <cuda_fp16.h>
#include <math.h>
#include <stdint.h>

#define B_  4
#define S_  2048
#define D_  2048
#define H_  16
#define DH_ 128
#define M_  (B_*S_)

// Scratch (allowed: __device__ globals)
__device__ __half g_qh[(size_t)B_*H_*S_*DH_];   // Q unroped fp16 [bh][s][dh]
__device__ __half g_kh0[(size_t)B_*H_*S_*DH_];  // K unroped fp16
__device__ __half g_kh[(size_t)B_*H_*S_*DH_];   // K roped fp16
__device__ __half g_vh[(size_t)B_*H_*DH_*S_];   // V transposed [bh][dh][s] fp16
__device__ __half g_ctxh[(size_t)B_*S_*D_];     // ctx fp16
__device__ __half g_xh[(size_t)M_*D_];          // x fp16
__device__ __half g_w3h[(size_t)3*D_*D_];       // wq|wk|wv fp16; wo reuses [0]
__device__ float  g_cos[(size_t)S_*64];
__device__ float  g_sin[(size_t)S_*64];

// ---------------------------------------------------------------------------
// Helpers
// ---------------------------------------------------------------------------
__device__ __forceinline__ uint32_t f22h2(float a, float b) {
    __half2 h = __floats2half2_rn(a, b);
    return *reinterpret_cast<uint32_t*>(&h);
}

__device__ __forceinline__ void mma_f16(float c[4], const uint32_t a[4], const uint32_t b[2]) {
    asm volatile(
        "mma.sync.aligned.m16n8k16.row.col.f32.f16.f16.f32 "
        "{%0,%1,%2,%3}, {%4,%5,%6,%7}, {%8,%9}, {%0,%1,%2,%3};"
        : "+f"(c[0]), "+f"(c[1]), "+f"(c[2]), "+f"(c[3])
        : "r"(a[0]), "r"(a[1]), "r"(a[2]), "r"(a[3]), "r"(b[0]), "r"(b[1]));
}

__device__ __forceinline__ void cp16(uint32_t dst, const void* src) {
    asm volatile("cp.async.cg.shared.global [%0], [%1], 16;" :: "r"(dst), "l"(src));
}

// ---------------------------------------------------------------------------
// f32 -> fp16 convert (4 elems/thread)
// ---------------------------------------------------------------------------
__global__ __launch_bounds__(256)
void tohalf_kernel(const float* __restrict__ in, __half* __restrict__ out)
{
    const int i = blockIdx.x * blockDim.x + threadIdx.x;
    float4 v = ((const float4*)in)[i];
    uint2 o;
    o.x = f22h2(v.x, v.y);
    o.y = f22h2(v.z, v.w);
    ((uint2*)out)[i] = o;
}

// ---------------------------------------------------------------------------
// FP16 GEMM: 128x128 CTA, 128 threads (2x2 warps, 64x64 warp tile), BK=64,
// 2-stage cp.async (73.7KB smem -> 3 CTAs/SM), stride-36 u32 rows.
// OUT=0: flat f32 Cf = A·Wᵀ + b0.
// OUT=1: merged QKV (N=6144): which = n0>>11; q -> Chq fp16 heads,
//        k -> Chk fp16 heads, v -> Chv fp16 transposed [bh][dh][s].
// ---------------------------------------------------------------------------
#define GBK 64

template<int OUT>
__global__ __launch_bounds__(128)
void gemm_f16(const __half* __restrict__ A, const __half* __restrict__ W,
              const float* __restrict__ b0, const float* __restrict__ b1,
              const float* __restrict__ b2,
              float* __restrict__ Cf, __half* __restrict__ Chq,
              __half* __restrict__ Chk, __half* __restrict__ Chv)
{
    __shared__ uint32_t As[2][128][36];   // 32 u32 = 64 halves + pad
    __shared__ uint32_t Ws[2][128][36];
    const int K  = D_;
    const int m0 = blockIdx.y * 128;
    const int n0 = blockIdx.x * 128;
    const int tid  = threadIdx.x;
    const int warp = tid >> 5, lane = tid & 31;
    const int wy = warp >> 1, wx = warp & 1;
    const int lr = lane >> 2, lc = lane & 3;

    float acc[4][8][4];
#pragma unroll
    for (int ti = 0; ti < 4; ti++)
#pragma unroll
        for (int nt = 0; nt < 8; nt++)
#pragma unroll
            for (int e = 0; e < 4; e++) acc[ti][nt][e] = 0.f;

    auto issue = [&](int st, int k0) {
#pragma unroll
        for (int u = 0; u < 8; u++) {     // A: 128 rows x 8 chunks (16B = 8 halves)
            const int f = tid + u * 128;
            const int r = f >> 3, c8 = f & 7;
            cp16((uint32_t)__cvta_generic_to_shared(&As[st][r][c8 * 4]),
                 A + (size_t)(m0 + r) * K + k0 + c8 * 8);
        }
#pragma unroll
        for (int u = 0; u < 8; u++) {
            const int f = tid + u * 128;
            const int r = f >> 3, c8 = f & 7;
            cp16((uint32_t)__cvta_generic_to_shared(&Ws[st][r][c8 * 4]),
                 W + (size_t)(n0 + r) * K + k0 + c8 * 8);
        }
        asm volatile("cp.async.commit_group;");
    };

    issue(0, 0);

    const int NIT = K / GBK;              // 32
#pragma unroll 1
    for (int it = 0; it < NIT; it++) {
        asm volatile("cp.async.wait_group 0;");
        __syncthreads();
        if (it + 1 < NIT) issue((it + 1) & 1, (it + 1) * GBK);
        const int cur = it & 1;

#pragma unroll
        for (int kk = 0; kk < 32; kk += 8) {    // four k16 steps (u32 cols)
            uint32_t afr[4][4], bfr[8][2];
            const int ac = kk + lc;
#pragma unroll
            for (int ti = 0; ti < 4; ti++) {
                const int ar = wy * 64 + ti * 16 + lr;
                afr[ti][0] = As[cur][ar    ][ac];
                afr[ti][1] = As[cur][ar + 8][ac];
                afr[ti][2] = As[cur][ar    ][ac + 4];
                afr[ti][3] = As[cur][ar + 8][ac + 4];
            }
#pragma unroll
            for (int nt = 0; nt < 8; nt++) {
                const int br = wx * 64 + nt * 8 + lr;
                bfr[nt][0] = Ws[cur][br][ac];
                bfr[nt][1] = Ws[cur][br][ac + 4];
            }
#pragma unroll
            for (int ti = 0; ti < 4; ti++)
#pragma unroll
                for (int nt = 0; nt < 8; nt++)
                    mma_f16(acc[ti][nt], afr[ti], bfr[nt]);
        }
    }

    // ---- epilogue: CTA lies entirely in one 2048-col segment for OUT=1 ----
    const int which = n0 >> 11;
    const float* bias = (OUT == 1) ? (which == 0 ? b0 : which == 1 ? b1 : b2) : b0;
    __half* Chqk = (which == 0) ? Chq : Chk;

#pragma unroll
    for (int ti = 0; ti < 4; ti++) {
#pragma unroll
        for (int nt = 0; nt < 8; nt++) {
            const int row = m0 + wy * 64 + ti * 16 + lr;
            const int col = n0 + wx * 64 + nt * 8 + lc * 2;
#pragma unroll
            for (int e = 0; e < 4; e++) {
                const int m = row + (e >> 1) * 8;
                const int n = col + (e & 1);
                const int nn = n & 2047;
                const float v = acc[ti][nt][e] + bias[OUT == 1 ? nn : n];
                if (OUT == 1) {
                    const int bb = m >> 11, s = m & (S_ - 1);
                    const int h = nn >> 7, dh = nn & 127;
                    if (which == 2)
                        Chv[(((size_t)(bb * H_ + h)) * DH_ + dh) * S_ + s] = __float2half_rn(v);
                    else
                        Chqk[(((size_t)bb * H_ + h) * S_ + s) * DH_ + dh] = __float2half_rn(v);
                } else {
                    Cf[(size_t)m * D_ + n] = v;
                }
            }
        }
    }
}

// ---------------------------------------------------------------------------
// RoPE table + K pre-rope (fp16 in, f32 math, fp16 out)
// ---------------------------------------------------------------------------
__global__ __launch_bounds__(256)
void rope_table_kernel()
{
    const int idx = blockIdx.x * blockDim.x + threadIdx.x;
    const int p = idx & 63;
    const int s = idx >> 6;
    const float invf = (float)exp(-(double)p * (log(10000.0) / 64.0));
    const float ang  = (float)s * invf;
    g_cos[idx] = (float)cos((double)ang);
    g_sin[idx] = (float)sin((double)ang);
}

__global__ __launch_bounds__(256)
void rope_k_kernel()
{
    const int idx = blockIdx.x * blockDim.x + threadIdx.x;  // B*H*S*64
    const int p   = idx & 63;
    const int row = idx >> 6;
    const int s   = row & (S_ - 1);
    const float cs = g_cos[s * 64 + p];
    const float sn = g_sin[s * 64 + p];
    const __half* kb = g_kh0 + (size_t)row * DH_;
    __half* kr = g_kh + (size_t)row * DH_;
    const float k1 = __half2float(kb[p]), k2 = __half2float(kb[p + 64]);
    kr[p]      = __float2half_rn(k1 * cs - k2 * sn);
    kr[p + 64] = __float2half_rn(k2 * cs + k1 * sn);
}

// ---------------------------------------------------------------------------
// FP16 flash attention (R15-proven): 256 threads / 8 warps, 128 q-rows/CTA,
// 64-key KV tiles double-buffered via cp.async. 90KB smem -> 2 CTAs/SM.
// Q staged from fp16 with fused rope.
// ---------------------------------------------------------------------------
#define KPADU 68
#define VPADU 36
#define PPADU 36
#define SMEM_ATTN ((128*KPADU + 2*128*VPADU + 128*PPADU) * 4)

__global__ __launch_bounds__(256)
void attn_f16()
{
    extern __shared__ uint32_t smu[];
    uint32_t* KB = smu;                         // Q staging 128 rows / 2x64-row K bufs
    uint32_t* VB = smu + 128 * KPADU;           // 2 x 128 x VPADU
    uint32_t* Ps = VB + 2 * 128 * VPADU;        // 128 x PPADU

    const int bh  = blockIdx.y;
    const int m0  = blockIdx.x * 128;
    const int tid = threadIdx.x;
    const int warp = tid >> 5, lane = tid & 31;
    const int lr = lane >> 2, lc = lane & 3;
    const int qr = warp * 16;

    const __half* Qh = g_qh + (size_t)bh * S_ * DH_;
    const __half* Kh = g_kh + (size_t)bh * S_ * DH_;
    const __half* Vh = g_vh + (size_t)bh * DH_ * S_;

    const float scale = 0.08838834764831845f;   // 1/sqrt(128)

    // ---- stage Q (fp16) with fused rope, scaled, into KB ----
#pragma unroll
    for (int i = 0; i < 8; i++) {
        const int idx = tid + i * 256;          // 128 rows x 16 pair-chunks
        const int r  = idx >> 4;
        const int p4 = idx & 15;
        const int s  = m0 + r;
        const uint2 u1 = *(const uint2*)(Qh + (size_t)s * DH_ + p4 * 4);
        const uint2 u2 = *(const uint2*)(Qh + (size_t)s * DH_ + p4 * 4 + 64);
        const float2 a01 = __half22float2(*(const __half2*)&u1.x);
        const float2 a23 = __half22float2(*(const __half2*)&u1.y);
        const float2 b01 = __half22float2(*(const __half2*)&u2.x);
        const float2 b23 = __half22float2(*(const __half2*)&u2.y);
        const float4 cs = *(const float4*)(g_cos + s * 64 + p4 * 4);
        const float4 sn = *(const float4*)(g_sin + s * 64 + p4 * 4);
        uint2 lo, hi;
        lo.x = f22h2((a01.x * cs.x - b01.x * sn.x) * scale,
                     (a01.y * cs.y - b01.y * sn.y) * scale);
        lo.y = f22h2((a23.x * cs.z - b23.x * sn.z) * scale,
                     (a23.y * cs.w - b23.y * sn.w) * scale);
        hi.x = f22h2((b01.x * cs.x + a01.x * sn.x) * scale,
                     (b01.y * cs.y + a01.y * sn.y) * scale);
        hi.y = f22h2((b23.x * cs.z + a23.x * sn.z) * scale,
                     (b23.y * cs.w + a23.y * sn.w) * scale);
        *(uint2*)(&KB[r * KPADU + p4 * 2])      = lo;
        *(uint2*)(&KB[r * KPADU + 32 + p4 * 2]) = hi;
    }
    __syncthreads();
    uint32_t qf[8][4];
#pragma unroll
    for (int ks = 0; ks < 8; ks++) {
        const int ac = ks * 8 + lc;
        qf[ks][0] = KB[(qr + lr    ) * KPADU + ac];
        qf[ks][1] = KB[(qr + lr + 8) * KPADU + ac];
        qf[ks][2] = KB[(qr + lr    ) * KPADU + ac + 4];
        qf[ks][3] = KB[(qr + lr + 8) * KPADU + ac + 4];
    }
    __syncthreads();   // Q consumed before K tiles overwrite KB

    auto issue_tile = [&](int t) {
        const int buf = t & 1;
        const int key0 = t * 64;
        uint32_t* kb = KB + buf * 64 * KPADU;
        uint32_t* vb = VB + buf * 128 * VPADU;
#pragma unroll
        for (int u = 0; u < 4; u++) {           // K: 64 rows x 16 chunks
            const int c = tid + u * 256;
            const int r = c >> 4, c8 = c & 15;
            cp16((uint32_t)__cvta_generic_to_shared(&kb[r * KPADU + c8 * 4]),
                 Kh + (size_t)(key0 + r) * DH_ + c8 * 8);
        }
#pragma unroll
        for (int u = 0; u < 4; u++) {           // V: 128 rows x 8 chunks
            const int c = tid + u * 256;
            const int r = c >> 3, c8 = c & 7;
            cp16((uint32_t)__cvta_generic_to_shared(&vb[r * VPADU + c8 * 4]),
                 Vh + (size_t)r * S_ + key0 + c8 * 8);
        }
        asm volatile("cp.async.commit_group;");
    };

    issue_tile(0);
    issue_tile(1);

    float oacc[16][4];
#pragma unroll
    for (int nt = 0; nt < 16; nt++)
#pragma unroll
        for (int e = 0; e < 4; e++) oacc[nt][e] = 0.f;
    float mr0 = -1e30f, mr1 = -1e30f, lsum0 = 0.f, lsum1 = 0.f;

#pragma unroll 1
    for (int kt = 0; kt < 32; kt++) {
        asm volatile("cp.async.wait_group %0;" :: "n"(1));
        __syncthreads();
        const int buf = kt & 1;
        const uint32_t* kb = KB + buf * 64 * KPADU;
        const uint32_t* vb = VB + buf * 128 * VPADU;

        // ---- S = Q·Kᵀ ----
        float sacc[8][4];
#pragma unroll
        for (int n = 0; n < 8; n++)
#pragma unroll
            for (int e = 0; e < 4; e++) sacc[n][e] = 0.f;
#pragma unroll
        for (int ks = 0; ks < 8; ks++) {
            const int ac = ks * 8 + lc;
#pragma unroll
            for (int n = 0; n < 8; n++) {
                uint32_t b[2];
                b[0] = kb[(n * 8 + lr) * KPADU + ac];
                b[1] = kb[(n * 8 + lr) * KPADU + ac + 4];
                mma_f16(sacc[n], qf[ks], b);
            }
        }

        // ---- online softmax ----
        float mx0 = mr0, mx1 = mr1;
#pragma unroll
        for (int n = 0; n < 8; n++) {
            mx0 = fmaxf(mx0, fmaxf(sacc[n][0], sacc[n][1]));
            mx1 = fmaxf(mx1, fmaxf(sacc[n][2], sacc[n][3]));
        }
        mx0 = fmaxf(mx0, __shfl_xor_sync(0xffffffffu, mx0, 1));
        mx0 = fmaxf(mx0, __shfl_xor_sync(0xffffffffu, mx0, 2));
        mx1 = fmaxf(mx1, __shfl_xor_sync(0xffffffffu, mx1, 1));
        mx1 = fmaxf(mx1, __shfl_xor_sync(0xffffffffu, mx1, 2));
        const float f0 = __expf(mr0 - mx0);
        const float f1 = __expf(mr1 - mx1);
        mr0 = mx0; mr1 = mx1;

        float s0 = 0.f, s1 = 0.f;
#pragma unroll
        for (int n = 0; n < 8; n++) {
            const float p0 = __expf(sacc[n][0] - mx0);
            const float p1 = __expf(sacc[n][1] - mx0);
            const float p2 = __expf(sacc[n][2] - mx1);
            const float p3 = __expf(sacc[n][3] - mx1);
            s0 += p0 + p1; s1 += p2 + p3;
            Ps[(qr + lr    ) * PPADU + n * 4 + lc] = f22h2(p0, p1);
            Ps[(qr + lr + 8) * PPADU + n * 4 + lc] = f22h2(p2, p3);
        }
        s0 += __shfl_xor_sync(0xffffffffu, s0, 1);
        s0 += __shfl_xor_sync(0xffffffffu, s0, 2);
        s1 += __shfl_xor_sync(0xffffffffu, s1, 1);
        s1 += __shfl_xor_sync(0xffffffffu, s1, 2);
        lsum0 = lsum0 * f0 + s0;
        lsum1 = lsum1 * f1 + s1;
#pragma unroll
        for (int nt = 0; nt < 16; nt++) {
            oacc[nt][0] *= f0; oacc[nt][1] *= f0;
            oacc[nt][2] *= f1; oacc[nt][3] *= f1;
        }
        __syncwarp();  // own-warp P stores before P fragment loads

        // ---- O += P·V ----
#pragma unroll
        for (int kk = 0; kk < 4; kk++) {
            const int ac = kk * 8 + lc;
            uint32_t af[4];
            af[0] = Ps[(qr + lr    ) * PPADU + ac];
            af[1] = Ps[(qr + lr + 8) * PPADU + ac];
            af[2] = Ps[(qr + lr    ) * PPADU + ac + 4];
            af[3] = Ps[(qr + lr + 8) * PPADU + ac + 4];
#pragma unroll
            for (int nt = 0; nt < 16; nt++) {
                uint32_t b[2];
                b[0] = vb[(nt * 8 + lr) * VPADU + ac];
                b[1] = vb[(nt * 8 + lr) * VPADU + ac + 4];
                mma_f16(oacc[nt], af, b);
            }
        }

        __syncthreads();
        if (kt + 2 < 32) {
            issue_tile(kt + 2);
        } else {
            asm volatile("cp.async.commit_group;");
        }
    }

    // ---- epilogue: normalize, fp16 ctx ----
    const float i0 = 1.f / lsum0, i1 = 1.f / lsum1;
    const int bb = bh >> 4, h = bh & 15;
    const int gr0 = m0 + qr + lr;
    uint32_t* ctxu = (uint32_t*)g_ctxh;
    uint32_t* o0 = ctxu + ((size_t)bb * S_ + gr0) * (D_ / 2) + h * 64;
    uint32_t* o1 = o0 + (size_t)8 * (D_ / 2);
#pragma unroll
    for (int nt = 0; nt < 16; nt++) {
        o0[nt * 4 + lc] = f22h2(oacc[nt][0] * i0, oacc[nt][1] * i0);
        o1[nt * 4 + lc] = f22h2(oacc[nt][2] * i1, oacc[nt][3] * i1);
    }
}

// ---------------------------------------------------------------------------
extern "C" void kernel_launch(void* const* d_in, const int* in_sizes, int n_in,
                              void* d_out, int out_size)
{
    const float* x  = (const float*)d_in[0];
    const float* wq = (const float*)d_in[1];
    const float* bq = (const float*)d_in[2];
    const float* wk = (const float*)d_in[3];
    const float* bk = (const float*)d_in[4];
    const float* wv = (const float*)d_in[5];
    const float* bv = (const float*)d_in[6];
    const float* wo = (const float*)d_in[7];
    const float* bo = (const float*)d_in[8];
    float* out = (float*)d_out;

    __half *qh, *kh0, *kh, *vh, *ctxh, *xh, *w3h;
    cudaGetSymbolAddress((void**)&qh,   g_qh);
    cudaGetSymbolAddress((void**)&kh0,  g_kh0);
    cudaGetSymbolAddress((void**)&kh,   g_kh);
    cudaGetSymbolAddress((void**)&vh,   g_vh);
    cudaGetSymbolAddress((void**)&ctxh, g_ctxh);
    cudaGetSymbolAddress((void**)&xh,   g_xh);
    cudaGetSymbolAddress((void**)&w3h,  g_w3h);

    cudaFuncSetAttribute(attn_f16, cudaFuncAttributeMaxDynamicSharedMemorySize, SMEM_ATTN);

    const int XB = (M_ * D_) / 4 / 256;
    const int WB = (D_ * D_) / 4 / 256;

    rope_table_kernel<<<(S_ * 64) / 256, 256>>>();
    tohalf_kernel<<<XB, 256>>>(x, xh);
    tohalf_kernel<<<WB, 256>>>(wq, w3h);
    tohalf_kernel<<<WB, 256>>>(wk, w3h + (size_t)D_ * D_);
    tohalf_kernel<<<WB, 256>>>(wv, w3h + (size_t)2 * D_ * D_);

    // merged QKV projection: N = 6144
    gemm_f16<1><<<dim3(6144 / 128, M_ / 128), 128>>>(
        xh, w3h, bq, bk, bv, nullptr, qh, kh0, vh);

    rope_k_kernel<<<(B_ * H_ * S_ * 64) / 256, 256>>>();  // g_kh0 -> g_kh roped

    attn_f16<<<dim3(S_ / 128, B_ * H_), 256, SMEM_ATTN>>>();

    tohalf_kernel<<<WB, 256>>>(wo, w3h);
    gemm_f16<0><<<dim3(D_ / 128, M_ / 128), 128>>>(
        ctxh, w3h, bo, bo, bo, out, nullptr, nullptr, nullptr);
}